// round 11
// baseline (speedup 1.0000x reference)
#include <cuda_runtime.h>
#include <math.h>

// Problem dims (fixed by setup_inputs)
#define NB   8
#define NG   1024
#define NK   32
#define NC   168
#define NFD  56
#define NCH  336
#define GKS  (NG * NK)     // 32768
#define NBG  (NB * NG)     // 8192

#define GRID_R 1024        // 8 bg rows per block

// Per-block partials: [sx, sx2, sz, sz2]; last-block finalize pattern.
__device__ double       g_part[GRID_R][4];
__device__ unsigned int g_cnt = 0;
__device__ float        g_inv[2];   // [0]=1/(std_x+eps), [1]=1/(std_xyz+eps)

// ---------------------------------------------------------------------------
// Precise fast sincos: Cody-Waite reduction by 2*pi, then MUFU sin/cos.
// ---------------------------------------------------------------------------
namespace cw {
constexpr double TWO_PI_D = 6.283185307179586476925286766559;
constexpr float  RED_A = 6.28125f;                                       // exact
constexpr float  RED_B = (float)(TWO_PI_D - (double)RED_A);
constexpr float  RED_C = (float)(TWO_PI_D - (double)RED_A - (double)RED_B);
constexpr float  INV_2PI = 0.15915494309189535f;
}

__device__ __forceinline__ void fsincos(float x, float& s, float& c) {
    float n = rintf(x * cw::INV_2PI);
    float y = fmaf(n, -cw::RED_A, x);
    y = fmaf(n, -cw::RED_B, y);
    y = fmaf(n, -cw::RED_C, y);
    s = __sinf(y);
    c = __cosf(y);
}

// log2(1000)/56
constexpr float K_LOG2A_FD = 0.17796043365468013f;

// ---------------------------------------------------------------------------
// Reduction kernel: each block owns 8 contiguous bg rows (172KB chunk).
// Plain (caching) loads: the tail of knn_x stays in L2 for k_main.
// ---------------------------------------------------------------------------
__device__ __forceinline__ void warp_reduce4(double& a, double& b,
                                             double& c, double& d) {
    #pragma unroll
    for (int o = 16; o; o >>= 1) {
        a += __shfl_down_sync(0xffffffffu, a, o);
        b += __shfl_down_sync(0xffffffffu, b, o);
        c += __shfl_down_sync(0xffffffffu, c, o);
        d += __shfl_down_sync(0xffffffffu, d, o);
    }
}

__global__ __launch_bounds__(512)
void k_reduce(const float4* __restrict__ knn_x4,
              const float*  __restrict__ lc_x,
              const float*  __restrict__ knn_xyz,
              const float*  __restrict__ lc_xyz) {
    const int t   = threadIdx.x;
    const int bg0 = blockIdx.x * 8;
    const float4* kx4 = knn_x4 + (size_t)bg0 * 1344;   // 8 rows * 1344 float4

    __shared__ float4 slc[336];                         // 8 lc rows (42 each)
    if (t < 336) slc[t] = ((const float4*)lc_x)[bg0 * 42 + t];
    __syncthreads();

    float sx = 0.0f, sx2 = 0.0f;
    #pragma unroll 7
    for (int it = 0; it < 21; ++it) {                   // 21*512 = 10752 exact
        int j = t + it * 512;
        float4 v = kx4[j];
        float4 l = slc[(j / 1344) * 42 + j % 42];       // 1344 % 42 == 0
        float d0 = v.x - l.x, d1 = v.y - l.y, d2 = v.z - l.z, d3 = v.w - l.w;
        sx  += (d0 + d1) + (d2 + d3);
        sx2 += (d0 * d0 + d1 * d1) + (d2 * d2 + d3 * d3);
    }

    float sz = 0.0f, sz2 = 0.0f;
    #pragma unroll
    for (int i = t; i < 768; i += 512) {                // 8 bg * 96 xyz floats
        int bgl = i / 96;
        int d   = i % 3;
        float v = knn_xyz[bg0 * 96 + i] - __ldg(lc_xyz + (bg0 + bgl) * 3 + d);
        sz  += v;
        sz2 += v * v;
    }

    double a = sx, b = sx2, c = sz, d = sz2;
    warp_reduce4(a, b, c, d);
    __shared__ double sh[16][4];
    int w = t >> 5;
    if ((t & 31) == 0) { sh[w][0] = a; sh[w][1] = b; sh[w][2] = c; sh[w][3] = d; }
    __syncthreads();
    if (t == 0) {
        double r0 = 0, r1 = 0, r2 = 0, r3 = 0;
        #pragma unroll
        for (int i = 0; i < 16; i++) {
            r0 += sh[i][0]; r1 += sh[i][1]; r2 += sh[i][2]; r3 += sh[i][3];
        }
        g_part[blockIdx.x][0] = r0; g_part[blockIdx.x][1] = r1;
        g_part[blockIdx.x][2] = r2; g_part[blockIdx.x][3] = r3;
    }
    __threadfence();

    __shared__ int is_last;
    if (t == 0) is_last = (atomicAdd(&g_cnt, 1u) == GRID_R - 1) ? 1 : 0;
    __syncthreads();
    if (!is_last) return;

    double a2 = 0, b2 = 0, c2 = 0, d2 = 0;
    for (int i = t; i < GRID_R; i += 512) {
        a2 += g_part[i][0]; b2 += g_part[i][1];
        c2 += g_part[i][2]; d2 += g_part[i][3];
    }
    warp_reduce4(a2, b2, c2, d2);
    if ((t & 31) == 0) { sh[w][0] = a2; sh[w][1] = b2; sh[w][2] = c2; sh[w][3] = d2; }
    __syncthreads();
    if (t == 0) {
        double r0 = 0, r1 = 0, r2 = 0, r3 = 0;
        #pragma unroll
        for (int i = 0; i < 16; i++) {
            r0 += sh[i][0]; r1 += sh[i][1]; r2 += sh[i][2]; r3 += sh[i][3];
        }
        const double nx = (double)NB * NG * NK * NC;
        const double nz = (double)NB * NG * NK * 3;
        double vx = (r1 - r0 * r0 / nx) / (nx - 1.0);
        double vz = (r3 - r2 * r2 / nz) / (nz - 1.0);
        g_inv[0] = (float)(1.0 / (sqrt(vx) + 1e-5));
        g_inv[1] = (float)(1.0 / (sqrt(vz) + 1e-5));
        g_cnt = 0;                           // reset for next graph replay
    }
}

// ---------------------------------------------------------------------------
// Main kernel: one block per (b,g), walked in REVERSE bg order so the first
// wave hits the knn_x tail still resident in L2 after k_reduce.
// 256 threads, ~25.4KB smem, launch_bounds(256,8) -> <=32 regs, 100% occ.
// smem (floats):
//   s_w   [32][177] : cols 0..167 = normalized knn_x (k-major);
//                     cols 169..175 = 7-ch geometric embedding
//   s_xn  [3][32]   : normalized knn_xyz [d][k]
//   s_lct [336]     : lc-side trig per channel
//   s_inv [56]      : 1/alpha^(f/56)
//   s_tab [336]     : per-channel wv column index (int bits)
// ---------------------------------------------------------------------------
#define SW_STRIDE 177
#define S_W     0
#define S_XN    (S_W + NK * SW_STRIDE)       // 5664
#define S_LCT   (S_XN + 3 * NK)              // 5760
#define S_INV   (S_LCT + NCH)                // 6096
#define S_TAB   (S_INV + NFD)                // 6152
#define SMEM_FLOATS (S_TAB + NCH)            // 6488 (~25.4 KB)

__global__ __launch_bounds__(256, 8)
void k_main(const float* __restrict__ lc_xyz, const float* __restrict__ lc_x,
            const float* __restrict__ knn_xyz, const float* __restrict__ knn_x,
            float* __restrict__ out) {
    __shared__ float sm[SMEM_FLOATS];
    const int bg = NBG - 1 - blockIdx.x;     // reverse order for L2 reuse
    const int t  = threadIdx.x;

    const float inv_x = g_inv[0];
    const float inv_z = g_inv[1];

    // ---- phase 1: stage into smem ------------------------------------------
    if (t < NFD)
        sm[S_INV + t] = 1.0f / exp2f((float)t * K_LOG2A_FD);

    if (t < 3 * NK) {                         // normalized knn_xyz [d][k]
        int d = t % 3, k = t / 3;
        float v = knn_xyz[bg * (NK * 3) + t] - __ldg(lc_xyz + bg * 3 + d);
        sm[S_XN + d * NK + k] = v * inv_z;
    }

    if (t < 3 * NFD) {                        // lc-side trig (raw lc_xyz)
        int d = t / NFD, f = t % NFD;
        float inv = 1.0f / exp2f((float)f * K_LOG2A_FD);
        float a = 100.0f * __ldg(lc_xyz + bg * 3 + d) * inv;
        float sn, cs;
        fsincos(a, sn, cs);
        sm[S_LCT + d * 112 + f]      = sn;
        sm[S_LCT + d * 112 + 56 + f] = cs;
    }

    // wv column table — full 336 entries with strided loop
    for (int i = t; i < NCH; i += 256) {
        int col = (i < NC) ? i : (169 + (i - NC) % 7);
        sm[S_TAB + i] = __int_as_float(col);
    }

    // normalized knn_x -> s_w[k][c], row stride 177 (caching loads: L2 hits)
    {
        const float4* kx4 = (const float4*)(knn_x + (size_t)bg * NK * NC);
        const float4* lx4 = (const float4*)(lc_x + (size_t)bg * NC);
        #pragma unroll
        for (int it = 0; it < 6; ++it) {
            int i = t + it * 256;
            if (i < NK * NC / 4) {            // 1344
                int k  = i / 42;
                int c4 = i - k * 42;
                float4 v = kx4[i];
                float4 l = lx4[c4];
                float* dst = &sm[S_W + k * SW_STRIDE + c4 * 4];
                dst[0] = (v.x - l.x) * inv_x;
                dst[1] = (v.y - l.y) * inv_x;
                dst[2] = (v.z - l.z) * inv_x;
                dst[3] = (v.w - l.w) * inv_x;
            }
        }
    }
    __syncthreads();

    // ---- phase 2: 7-ch geometric embedding -> s_w cols 169..175 ------------
    if (t < NK) {
        int k = t;
        float a0 = sm[S_XN + k], a1 = sm[S_XN + NK + k], a2 = sm[S_XN + 2 * NK + k];
        float b0 = __ldg(lc_xyz + bg * 3 + 0);
        float b1 = __ldg(lc_xyz + bg * 3 + 1);
        float b2 = __ldg(lc_xyz + bg * 3 + 2);
        float* row = &sm[S_W + k * SW_STRIDE + 169];
        row[0] = a0;
        row[1] = a1;
        row[2] = a2;
        row[3] = a1 * b2 - a2 * b1;
        row[4] = a2 * b0 - a0 * b2;
        row[5] = a0 * b1 - a1 * b0;
        row[6] = a0 * b0 + a1 * b1 + a2 * b2;
    }
    __syncthreads();

    // ---- phase 3: vectorized trig + output ---------------------------------
    // task = (df, kq): 168 * 8 tasks; 4 sincos, 2 float4 stores per task.
    const int b = bg >> 10;
    const int g = bg & (NG - 1);
    float* obase = out + (size_t)b * NCH * GKS + (size_t)g * NK;

    const int kq  = t & 7;
    const int k0  = kq * 4;
    const int df0 = t >> 3;                   // 0..31
    const int wbase = S_W + k0 * SW_STRIDE;

    #pragma unroll
    for (int it = 0; it < 6; ++it) {
        int df = df0 + it * 32;
        if (df < 3 * NFD) {
            int d = df / NFD;
            int f = df - d * NFD;
            float amp = 100.0f * sm[S_INV + f];
            const float4 x = *(const float4*)&sm[S_XN + d * NK + k0];
            float s0, c0, s1, c1, s2, c2, s3, c3;
            fsincos(amp * x.x, s0, c0);
            fsincos(amp * x.y, s1, c1);
            fsincos(amp * x.z, s2, c2);
            fsincos(amp * x.w, s3, c3);
            int cb1 = df + d * 56;            // d*112 + f
            int cb2 = cb1 + 56;
            float l1 = sm[S_LCT + cb1];
            float l2 = sm[S_LCT + cb2];
            int col1 = __float_as_int(sm[S_TAB + cb1]);
            int col2 = __float_as_int(sm[S_TAB + cb2]);
            float4 r1, r2;
            float p;
            p = s0 + l1; r1.x = (sm[wbase + 0 * SW_STRIDE + col1] + p) * p;
            p = s1 + l1; r1.y = (sm[wbase + 1 * SW_STRIDE + col1] + p) * p;
            p = s2 + l1; r1.z = (sm[wbase + 2 * SW_STRIDE + col1] + p) * p;
            p = s3 + l1; r1.w = (sm[wbase + 3 * SW_STRIDE + col1] + p) * p;
            p = c0 + l2; r2.x = (sm[wbase + 0 * SW_STRIDE + col2] + p) * p;
            p = c1 + l2; r2.y = (sm[wbase + 1 * SW_STRIDE + col2] + p) * p;
            p = c2 + l2; r2.z = (sm[wbase + 2 * SW_STRIDE + col2] + p) * p;
            p = c3 + l2; r2.w = (sm[wbase + 3 * SW_STRIDE + col2] + p) * p;
            __stcs((float4*)(obase + (size_t)cb1 * GKS + k0), r1);
            __stcs((float4*)(obase + (size_t)cb2 * GKS + k0), r2);
        }
    }
}

// ---------------------------------------------------------------------------
extern "C" void kernel_launch(void* const* d_in, const int* in_sizes, int n_in,
                              void* d_out, int out_size) {
    const float* lc_xyz  = (const float*)d_in[0];
    const float* lc_x    = (const float*)d_in[1];
    const float* knn_xyz = (const float*)d_in[2];
    const float* knn_x   = (const float*)d_in[3];
    float* out = (float*)d_out;

    k_reduce<<<GRID_R, 512>>>((const float4*)knn_x, lc_x, knn_xyz, lc_xyz);
    k_main<<<NBG, 256>>>(lc_xyz, lc_x, knn_xyz, knn_x, out);
}

// round 12
// speedup vs baseline: 1.0696x; 1.0696x over previous
#include <cuda_runtime.h>
#include <math.h>

// Problem dims (fixed by setup_inputs)
#define NB   8
#define NG   1024
#define NK   32
#define NC   168
#define NFD  56
#define NCH  336
#define GKS  (NG * NK)     // 32768
#define NBG  (NB * NG)     // 8192

// Persistent grid: 6 blocks/SM * 148 SMs -> all blocks resident (spin-safe)
#define GRID_F 888

__device__ double                g_part[GRID_F][4];
__device__ unsigned int          g_cnt  = 0;
__device__ volatile unsigned int g_done = 0;
__device__ float                 g_inv[2];

// ---------------------------------------------------------------------------
// Precise fast sincos: Cody-Waite reduction by 2*pi, then MUFU sin/cos.
// ---------------------------------------------------------------------------
namespace cw {
constexpr double TWO_PI_D = 6.283185307179586476925286766559;
constexpr float  RED_A = 6.28125f;                                       // exact
constexpr float  RED_B = (float)(TWO_PI_D - (double)RED_A);
constexpr float  RED_C = (float)(TWO_PI_D - (double)RED_A - (double)RED_B);
constexpr float  INV_2PI = 0.15915494309189535f;
}

__device__ __forceinline__ void fsincos(float x, float& s, float& c) {
    float n = rintf(x * cw::INV_2PI);
    float y = fmaf(n, -cw::RED_A, x);
    y = fmaf(n, -cw::RED_B, y);
    y = fmaf(n, -cw::RED_C, y);
    s = __sinf(y);
    c = __cosf(y);
}

// log2(1000)/56
constexpr float K_LOG2A_FD = 0.17796043365468013f;

__device__ __forceinline__ void warp_reduce4(double& a, double& b,
                                             double& c, double& d) {
    #pragma unroll
    for (int o = 16; o; o >>= 1) {
        a += __shfl_down_sync(0xffffffffu, a, o);
        b += __shfl_down_sync(0xffffffffu, b, o);
        c += __shfl_down_sync(0xffffffffu, c, o);
        d += __shfl_down_sync(0xffffffffu, d, o);
    }
}

// ---------------------------------------------------------------------------
// smem layout (floats) — as in the 151.6us kernel:
//   s_w   [32][177] : cols 0..167 normalized knn_x (k-major);
//                     cols 169..175 = 7-ch geometric embedding
//   s_xn  [3][32], s_lct[336], s_inv[56], s_tab[336]
// ---------------------------------------------------------------------------
#define SW_STRIDE 177
#define S_W     0
#define S_XN    (S_W + NK * SW_STRIDE)       // 5664
#define S_LCT   (S_XN + 3 * NK)              // 5760
#define S_INV   (S_LCT + NCH)                // 6096
#define S_TAB   (S_INV + NFD)                // 6152
#define SMEM_FLOATS (S_TAB + NCH)            // 6488 (~25.4 KB)

__global__ __launch_bounds__(256, 6)
void k_fused(const float* __restrict__ lc_xyz, const float* __restrict__ lc_x,
             const float* __restrict__ knn_xyz, const float* __restrict__ knn_x,
             float* __restrict__ out) {
    __shared__ float sm[SMEM_FLOATS];
    __shared__ double sh[8][4];
    __shared__ unsigned int s_epoch;
    __shared__ int s_last;

    const int t = threadIdx.x;

    // Epoch snapshot: every block reads BEFORE its own atomicAdd, which
    // happens-before the last block's publish -> all blocks see same epoch.
    if (t == 0) s_epoch = g_done;

    // Static tables (valid for whole kernel)
    if (t < NFD)
        sm[S_INV + t] = 1.0f / exp2f((float)t * K_LOG2A_FD);
    for (int i = t; i < NCH; i += 256) {
        int col = (i < NC) ? i : (169 + (i - NC) % 7);
        sm[S_TAB + i] = __int_as_float(col);
    }

    // ======================= PHASE A: global reduction ======================
    // Block b reduces tiles {b, b+888, ...} in ASCENDING order.
    float sx = 0.0f, sx2 = 0.0f, sz = 0.0f, sz2 = 0.0f;
    {
        const float4* kx4all = (const float4*)knn_x;
        const float4* lx4all = (const float4*)lc_x;
        for (int tile = blockIdx.x; tile < NBG; tile += GRID_F) {
            const float4* kx4 = kx4all + (size_t)tile * 1344;
            const float4* lx4 = lx4all + (size_t)tile * 42;
            #pragma unroll
            for (int it = 0; it < 6; ++it) {
                int i = t + it * 256;
                if (i < 1344) {
                    float4 v = kx4[i];
                    float4 l = __ldg(&lx4[i % 42]);
                    float d0 = v.x - l.x, d1 = v.y - l.y;
                    float d2 = v.z - l.z, d3 = v.w - l.w;
                    sx  += (d0 + d1) + (d2 + d3);
                    sx2 += (d0 * d0 + d1 * d1) + (d2 * d2 + d3 * d3);
                }
            }
            if (t < 96) {                    // 32 k * 3 dims
                float v = knn_xyz[tile * 96 + t]
                        - __ldg(lc_xyz + tile * 3 + t % 3);
                sz  += v;
                sz2 += v * v;
            }
        }
    }

    {   // block reduce -> per-block partial
        double a = sx, b = sx2, c = sz, d = sz2;
        warp_reduce4(a, b, c, d);
        int w = t >> 5;
        if ((t & 31) == 0) { sh[w][0]=a; sh[w][1]=b; sh[w][2]=c; sh[w][3]=d; }
        __syncthreads();
        if (t == 0) {
            double r0=0, r1=0, r2=0, r3=0;
            #pragma unroll
            for (int i = 0; i < 8; i++) {
                r0 += sh[i][0]; r1 += sh[i][1]; r2 += sh[i][2]; r3 += sh[i][3];
            }
            g_part[blockIdx.x][0]=r0; g_part[blockIdx.x][1]=r1;
            g_part[blockIdx.x][2]=r2; g_part[blockIdx.x][3]=r3;
            __threadfence();
            s_last = (atomicAdd(&g_cnt, 1u) == GRID_F - 1) ? 1 : 0;
        }
        __syncthreads();
    }

    if (s_last) {                            // last block finalizes
        double a2=0, b2=0, c2=0, d2=0;
        for (int i = t; i < GRID_F; i += 256) {
            a2 += g_part[i][0]; b2 += g_part[i][1];
            c2 += g_part[i][2]; d2 += g_part[i][3];
        }
        warp_reduce4(a2, b2, c2, d2);
        int w = t >> 5;
        if ((t & 31) == 0) { sh[w][0]=a2; sh[w][1]=b2; sh[w][2]=c2; sh[w][3]=d2; }
        __syncthreads();
        if (t == 0) {
            double r0=0, r1=0, r2=0, r3=0;
            #pragma unroll
            for (int i = 0; i < 8; i++) {
                r0 += sh[i][0]; r1 += sh[i][1]; r2 += sh[i][2]; r3 += sh[i][3];
            }
            const double nx = (double)NB * NG * NK * NC;
            const double nz = (double)NB * NG * NK * 3;
            double vx = (r1 - r0 * r0 / nx) / (nx - 1.0);
            double vz = (r3 - r2 * r2 / nz) / (nz - 1.0);
            ((volatile float*)g_inv)[0] = (float)(1.0 / (sqrt(vx) + 1e-5));
            ((volatile float*)g_inv)[1] = (float)(1.0 / (sqrt(vz) + 1e-5));
            g_cnt = 0;                       // reset for next replay
            __threadfence();
            g_done = s_epoch + 1;            // publish
        }
    }

    // Grid-wide spin barrier (all 888 blocks resident by construction)
    if (t == 0) {
        while (g_done == s_epoch) __nanosleep(64);
    }
    __syncthreads();
    const float inv_x = ((volatile float*)g_inv)[0];
    const float inv_z = ((volatile float*)g_inv)[1];

    // ======================= PHASE B: main computation ======================
    // Same tiles in REVERSE order: last-reduced tile is still L2-hot.
    const int ntiles = (NBG - blockIdx.x + GRID_F - 1) / GRID_F;
    for (int j = ntiles - 1; j >= 0; --j) {
        const int bg = blockIdx.x + j * GRID_F;

        // ---- stage tile into smem ----
        if (t < 3 * NK) {                     // normalized knn_xyz [d][k]
            int d = t % 3, k = t / 3;
            float v = knn_xyz[bg * (NK * 3) + t] - __ldg(lc_xyz + bg * 3 + d);
            sm[S_XN + d * NK + k] = v * inv_z;
        }
        if (t < 3 * NFD) {                    // lc-side trig (raw lc_xyz)
            int d = t / NFD, f = t % NFD;
            float inv = 1.0f / exp2f((float)f * K_LOG2A_FD);
            float a = 100.0f * __ldg(lc_xyz + bg * 3 + d) * inv;
            float sn, cs;
            fsincos(a, sn, cs);
            sm[S_LCT + d * 112 + f]      = sn;
            sm[S_LCT + d * 112 + 56 + f] = cs;
        }
        {
            const float4* kx4 = (const float4*)(knn_x + (size_t)bg * NK * NC);
            const float4* lx4 = (const float4*)(lc_x + (size_t)bg * NC);
            #pragma unroll
            for (int it = 0; it < 6; ++it) {
                int i = t + it * 256;
                if (i < NK * NC / 4) {        // 1344
                    int k  = i / 42;
                    int c4 = i - k * 42;
                    float4 v = kx4[i];        // L2 hit (phase A just read it)
                    float4 l = lx4[c4];
                    float* dst = &sm[S_W + k * SW_STRIDE + c4 * 4];
                    dst[0] = (v.x - l.x) * inv_x;
                    dst[1] = (v.y - l.y) * inv_x;
                    dst[2] = (v.z - l.z) * inv_x;
                    dst[3] = (v.w - l.w) * inv_x;
                }
            }
        }
        __syncthreads();

        // ---- 7-ch geometric embedding -> s_w cols 169..175 ----
        if (t < NK) {
            int k = t;
            float a0 = sm[S_XN + k], a1 = sm[S_XN + NK + k];
            float a2 = sm[S_XN + 2 * NK + k];
            float b0 = __ldg(lc_xyz + bg * 3 + 0);
            float b1 = __ldg(lc_xyz + bg * 3 + 1);
            float b2 = __ldg(lc_xyz + bg * 3 + 2);
            float* row = &sm[S_W + k * SW_STRIDE + 169];
            row[0] = a0;
            row[1] = a1;
            row[2] = a2;
            row[3] = a1 * b2 - a2 * b1;
            row[4] = a2 * b0 - a0 * b2;
            row[5] = a0 * b1 - a1 * b0;
            row[6] = a0 * b0 + a1 * b1 + a2 * b2;
        }
        __syncthreads();

        // ---- vectorized trig + output: (df, kq) -> 4 sincos, 2 STG.128 ----
        const int b = bg >> 10;
        const int g = bg & (NG - 1);
        float* obase = out + (size_t)b * NCH * GKS + (size_t)g * NK;

        const int kq  = t & 7;
        const int k0  = kq * 4;
        const int df0 = t >> 3;               // 0..31
        const int wbase = S_W + k0 * SW_STRIDE;

        #pragma unroll
        for (int it = 0; it < 6; ++it) {
            int df = df0 + it * 32;
            if (df < 3 * NFD) {
                int d = df / NFD;
                int f = df - d * NFD;
                float amp = 100.0f * sm[S_INV + f];
                const float4 x = *(const float4*)&sm[S_XN + d * NK + k0];
                float s0, c0, s1, c1, s2, c2, s3, c3;
                fsincos(amp * x.x, s0, c0);
                fsincos(amp * x.y, s1, c1);
                fsincos(amp * x.z, s2, c2);
                fsincos(amp * x.w, s3, c3);
                int cb1 = df + d * 56;        // d*112 + f
                int cb2 = cb1 + 56;
                float l1 = sm[S_LCT + cb1];
                float l2 = sm[S_LCT + cb2];
                int col1 = __float_as_int(sm[S_TAB + cb1]);
                int col2 = __float_as_int(sm[S_TAB + cb2]);
                float4 r1, r2;
                float p;
                p = s0 + l1; r1.x = (sm[wbase + 0 * SW_STRIDE + col1] + p) * p;
                p = s1 + l1; r1.y = (sm[wbase + 1 * SW_STRIDE + col1] + p) * p;
                p = s2 + l1; r1.z = (sm[wbase + 2 * SW_STRIDE + col1] + p) * p;
                p = s3 + l1; r1.w = (sm[wbase + 3 * SW_STRIDE + col1] + p) * p;
                p = c0 + l2; r2.x = (sm[wbase + 0 * SW_STRIDE + col2] + p) * p;
                p = c1 + l2; r2.y = (sm[wbase + 1 * SW_STRIDE + col2] + p) * p;
                p = c2 + l2; r2.z = (sm[wbase + 2 * SW_STRIDE + col2] + p) * p;
                p = c3 + l2; r2.w = (sm[wbase + 3 * SW_STRIDE + col2] + p) * p;
                __stcs((float4*)(obase + (size_t)cb1 * GKS + k0), r1);
                __stcs((float4*)(obase + (size_t)cb2 * GKS + k0), r2);
            }
        }
        __syncthreads();                      // s_w reused next tile
    }
}

// ---------------------------------------------------------------------------
extern "C" void kernel_launch(void* const* d_in, const int* in_sizes, int n_in,
                              void* d_out, int out_size) {
    const float* lc_xyz  = (const float*)d_in[0];
    const float* lc_x    = (const float*)d_in[1];
    const float* knn_xyz = (const float*)d_in[2];
    const float* knn_x   = (const float*)d_in[3];
    float* out = (float*)d_out;

    k_fused<<<GRID_F, 256>>>(lc_xyz, lc_x, knn_xyz, knn_x, out);
}